// round 6
// baseline (speedup 1.0000x reference)
#include <cuda_runtime.h>
#include <cuda_bf16.h>
#include <cstdint>

// Problem constants
#define B_WIN   1024
#define LTOK    49
#define CDIM    384
#define HEADS   12
#define HD      32
#define NWMASK  4
#define MTOT    (B_WIN * LTOK)          // 50176
#define QKVN    (3 * CDIM)              // 1152
#define KSPL    (3 * CDIM)              // 1152: [hi,lo,hi] x [hi,hi,lo] 3-term split
#define SCALE_F 19.595917942265426f     // sqrt(384)

// GEMM tiling (mma.sync bf16 path; tcgen05 unavailable on compute_103 PTX target)
#define BM 128
#define BN 128
#define BK 32
#define ROWB 80                          // 32 bf16 = 64B + 16B pad (conflict-free ldmatrix)
#define OPBYTES (128 * ROWB)             // 10240 per operand per stage
#define STG (2 * OPBYTES)                // 20480
#define DEPTH 4
#define NS (KSPL / BK)                   // 36
#define GSMEM (DEPTH * STG)              // 81920

// Scratch (device globals, allocation-free)
__device__ __align__(16) float          g_qkv[(size_t)MTOT * QKVN];   // 231 MB
__device__ __align__(16) __nv_bfloat16  g_a1[(size_t)MTOT * KSPL];    // 116 MB
__device__ __align__(16) __nv_bfloat16  g_a2[(size_t)MTOT * KSPL];    // 116 MB
__device__ __align__(16) __nv_bfloat16  g_b1[(size_t)QKVN * KSPL];    // 2.6 MB
__device__ __align__(16) __nv_bfloat16  g_b2[(size_t)CDIM * KSPL];    // 0.9 MB
__device__ __align__(16) float g_bias[HEADS * LTOK * LTOK];
__device__ unsigned long long g_maskbits[NWMASK * LTOK];

// ---------------------------------------------------------------------------
// Helpers
// ---------------------------------------------------------------------------
__device__ __forceinline__ uint32_t smem_u32(const void* p) {
    uint32_t a;
    asm("{ .reg .u64 t; cvta.to.shared.u64 t, %1; cvt.u32.u64 %0, t; }" : "=r"(a) : "l"(p));
    return a;
}
__device__ __forceinline__ void cp16(uint32_t dst, const void* src) {
    asm volatile("cp.async.cg.shared.global [%0], [%1], 16;" :: "r"(dst), "l"(src) : "memory");
}
__device__ __forceinline__ void cp_commit() { asm volatile("cp.async.commit_group;" ::: "memory"); }
template <int N> __device__ __forceinline__ void cp_wait() {
    asm volatile("cp.async.wait_group %0;" :: "n"(N) : "memory");
}
#define LDSM_X4(r0, r1, r2, r3, addr) \
    asm volatile("ldmatrix.sync.aligned.m8n8.x4.shared.b16 {%0,%1,%2,%3}, [%4];" \
                 : "=r"(r0), "=r"(r1), "=r"(r2), "=r"(r3) : "r"(addr))

__device__ __forceinline__ void mma16816(float* d, const uint32_t* a, const uint32_t* b) {
    asm volatile("mma.sync.aligned.m16n8k16.row.col.f32.bf16.bf16.f32 "
        "{%0,%1,%2,%3}, {%4,%5,%6,%7}, {%8,%9}, {%0,%1,%2,%3};"
        : "+f"(d[0]), "+f"(d[1]), "+f"(d[2]), "+f"(d[3])
        : "r"(a[0]), "r"(a[1]), "r"(a[2]), "r"(a[3]), "r"(b[0]), "r"(b[1]));
}

// ---------------------------------------------------------------------------
// Prep: mask dtype detect + bitmask pack + bias gather (validated)
// ---------------------------------------------------------------------------
__global__ void prep_kernel(const void* __restrict__ mask_raw,
                            const float* __restrict__ rel_bias,
                            const int* __restrict__ rel_coords)
{
    __shared__ int flagBad, flagFloat;
    int tid = threadIdx.x;
    if (tid == 0) { flagBad = 0; flagFloat = 0; }
    __syncthreads();

    const unsigned* mw = (const unsigned*)mask_raw;
    for (int i = tid; i < 2401; i += blockDim.x) {
        unsigned w = mw[i];
        if (w != 0u && w != 1u && w != 0x3F800000u) flagBad = 1;
        if (w == 0x3F800000u) flagFloat = 1;
    }
    __syncthreads();
    int mode = flagBad ? 2 : (flagFloat ? 1 : 0);

    const unsigned char* m8 = (const unsigned char*)mask_raw;
    const float* mf = (const float*)mask_raw;
    const int*   mi = (const int*)mask_raw;

    for (int idx = tid; idx < NWMASK * LTOK; idx += blockDim.x) {
        int w = idx / LTOK, i = idx % LTOK;
        unsigned long long bits = 0ull;
        for (int j = 0; j < LTOK; j++) {
            int g = (w * LTOK + i) * LTOK + j;
            bool v = (mode == 2) ? (m8[g] != 0)
                   : (mode == 1) ? (mf[g] != 0.0f)
                                 : (mi[g] != 0);
            if (v) bits |= (1ull << j);
        }
        g_maskbits[idx] = bits;
    }
    for (int idx = tid; idx < HEADS * LTOK * LTOK; idx += blockDim.x) {
        int h = idx / (LTOK * LTOK);
        int ij = idx % (LTOK * LTOK);
        g_bias[idx] = rel_bias[rel_coords[ij] * HEADS + h];
    }
}

// ---------------------------------------------------------------------------
// bf16 3-term split.  A: [hi, lo, hi]   B: [hi, hi, lo]
// ---------------------------------------------------------------------------
__global__ void split_a_kernel(const float* __restrict__ src,
                               __nv_bfloat16* __restrict__ dst, int total)
{
    int idx = blockIdx.x * blockDim.x + threadIdx.x;
    if (idx >= total) return;
    int r = idx / CDIM, c = idx % CDIM;
    float v = src[idx];
    __nv_bfloat16 hi = __float2bfloat16(v);
    __nv_bfloat16 lo = __float2bfloat16(v - __bfloat162float(hi));
    size_t base = (size_t)r * KSPL;
    dst[base + c]            = hi;
    dst[base + CDIM + c]     = lo;
    dst[base + 2 * CDIM + c] = hi;
}
__global__ void split_b_kernel(const float* __restrict__ src,
                               __nv_bfloat16* __restrict__ dst, int total)
{
    int idx = blockIdx.x * blockDim.x + threadIdx.x;
    if (idx >= total) return;
    int r = idx / CDIM, c = idx % CDIM;
    float v = src[idx];
    __nv_bfloat16 hi = __float2bfloat16(v);
    __nv_bfloat16 lo = __float2bfloat16(v - __bfloat162float(hi));
    size_t base = (size_t)r * KSPL;
    dst[base + c]            = hi;
    dst[base + CDIM + c]     = hi;
    dst[base + 2 * CDIM + c] = lo;
}

// ---------------------------------------------------------------------------
// mma.sync bf16 GEMM (TN): C[m][n] = sum_k A[m][k]*B[n][k] (+bias[n])
// 128x128 tile, BK=32, 8 warps (4x2), warp tile 32x64, cp.async 4-stage.
// ---------------------------------------------------------------------------
__global__ __launch_bounds__(256, 2)
void gemm_mma(const __nv_bfloat16* __restrict__ A, const __nv_bfloat16* __restrict__ B,
              const float* __restrict__ bias, float* __restrict__ C, int N)
{
    extern __shared__ __align__(16) char smem[];
    const uint32_t sb = smem_u32(smem);
    const int tid = threadIdx.x;
    const int lane = tid & 31, warp = tid >> 5;
    const int wr = warp >> 1, wc = warp & 1;
    const int m0 = blockIdx.y * BM, n0 = blockIdx.x * BN;

    const __nv_bfloat16* Ab = A + (size_t)m0 * KSPL;
    const __nv_bfloat16* Bb = B + (size_t)n0 * KSPL;

    const int lrow  = tid & 127;
    const int lc16a = tid >> 7;

    auto load_stage = [&](int st) {
        uint32_t buf = sb + (st % DEPTH) * STG;
        int kc = st * BK;
#pragma unroll
        for (int i = 0; i < 2; i++) {
            int c16 = lc16a + i * 2;
            uint32_t d = buf + lrow * ROWB + c16 * 16;
            const __nv_bfloat16* s = Ab + (size_t)lrow * KSPL + kc + c16 * 8;
            cp16(d, s);
            cp16(d + OPBYTES, Bb + (size_t)lrow * KSPL + kc + c16 * 8);
        }
        cp_commit();
    };

    float acc[2][8][4];
#pragma unroll
    for (int mt = 0; mt < 2; mt++)
#pragma unroll
        for (int j = 0; j < 8; j++)
#pragma unroll
            for (int q = 0; q < 4; q++) acc[mt][j][q] = 0.0f;

    load_stage(0);
    load_stage(1);
    load_stage(2);

    const uint32_t a_lane = (uint32_t)((wr * 32 + ((lane >> 3) & 1) * 8 + (lane & 7)) * ROWB
                                       + (lane >> 4) * 16);
    const uint32_t b_lane = (uint32_t)(OPBYTES
                                       + (wc * 64 + ((lane >> 4) & 1) * 8 + (lane & 7)) * ROWB
                                       + ((lane >> 3) & 1) * 16);

    for (int s = 0; s < NS; s++) {
        if (s < NS - 2)      cp_wait<2>();
        else if (s == NS - 2) cp_wait<1>();
        else                 cp_wait<0>();
        __syncthreads();
        if (s + 3 < NS) load_stage(s + 3);

        uint32_t buf = sb + (s % DEPTH) * STG;
#pragma unroll
        for (int ks = 0; ks < 2; ks++) {
            uint32_t ra[2][4];
#pragma unroll
            for (int mt = 0; mt < 2; mt++)
                LDSM_X4(ra[mt][0], ra[mt][1], ra[mt][2], ra[mt][3],
                        buf + a_lane + mt * 16 * ROWB + ks * 32);
            uint32_t rb[8][2];
#pragma unroll
            for (int nt = 0; nt < 4; nt++) {
                uint32_t r0, r1, r2, r3;
                LDSM_X4(r0, r1, r2, r3, buf + b_lane + nt * 16 * ROWB + ks * 32);
                rb[2 * nt][0] = r0; rb[2 * nt][1] = r1;
                rb[2 * nt + 1][0] = r2; rb[2 * nt + 1][1] = r3;
            }
#pragma unroll
            for (int mt = 0; mt < 2; mt++)
#pragma unroll
                for (int j = 0; j < 8; j++)
                    mma16816(acc[mt][j], ra[mt], rb[j]);
        }
    }

    const int g = lane >> 2, tq = lane & 3;
#pragma unroll
    for (int mt = 0; mt < 2; mt++) {
        int r0 = m0 + wr * 32 + mt * 16 + g;
#pragma unroll
        for (int j = 0; j < 8; j++) {
            int c0 = n0 + wc * 64 + j * 8 + 2 * tq;
            float2 v0 = make_float2(acc[mt][j][0], acc[mt][j][1]);
            float2 v1 = make_float2(acc[mt][j][2], acc[mt][j][3]);
            if (bias) {
                float b0 = bias[c0], b1 = bias[c0 + 1];
                v0.x += b0; v0.y += b1; v1.x += b0; v1.y += b1;
            }
            *(float2*)(C + (size_t)r0 * N + c0)       = v0;
            *(float2*)(C + (size_t)(r0 + 8) * N + c0) = v1;
        }
    }
}

// ---------------------------------------------------------------------------
// Fused window attention v2: register-blocked, 4 query rows per warp per
// sweep. Writes bf16 3-term split output directly ([hi, lo, hi]).
// ---------------------------------------------------------------------------
__global__ __launch_bounds__(128)
void attn_kernel(const float* __restrict__ qkv, __nv_bfloat16* __restrict__ a2)
{
    const int h = blockIdx.x;
    const int b = blockIdx.y;
    const int tid = threadIdx.x;

    __shared__ __align__(16) float qs[LTOK * 34];   // pad 34: float2-aligned rows
    __shared__ __align__(16) float ks[LTOK * 34];
    __shared__ __align__(16) float vs[LTOK * 33];   // pad 33: conflict-free scalar
    __shared__ float bs[LTOK * LTOK];
    __shared__ __align__(16) float prow[4][4][64];  // [warp][r][j]
    __shared__ unsigned long long mbs[LTOK];

    const float* base = qkv + (size_t)(b * LTOK) * QKVN + h * HD;
    for (int t = tid; t < LTOK * HD; t += 128) {
        int l = t >> 5, d = t & 31;
        qs[l * 34 + d] = base[(size_t)l * QKVN + d];
        ks[l * 34 + d] = base[(size_t)l * QKVN + CDIM + d];
        vs[l * 33 + d] = base[(size_t)l * QKVN + 2 * CDIM + d];
    }
    for (int t = tid; t < LTOK * LTOK; t += 128)
        bs[t] = g_bias[h * LTOK * LTOK + t];
    if (tid < LTOK) mbs[tid] = g_maskbits[(b & 3) * LTOK + tid];
    __syncthreads();

    const int warp = tid >> 5;
    const int lane = tid & 31;
    const bool valid1 = (lane + 32) < LTOK;
    const int j2 = valid1 ? lane + 32 : 0;

    for (int sweep = 0; sweep < 4; sweep++) {
        const int row0 = sweep * 16 + warp * 4;
        if (row0 >= LTOK) break;   // uniform per warp

        int rc[4];
#pragma unroll
        for (int r = 0; r < 4; r++) rc[r] = (row0 + r < LTOK) ? row0 + r : LTOK - 1;

        const float2* q0 = (const float2*)&qs[rc[0] * 34];
        const float2* q1 = (const float2*)&qs[rc[1] * 34];
        const float2* q2c = (const float2*)&qs[rc[2] * 34];
        const float2* q3 = (const float2*)&qs[rc[3] * 34];
        const float2* kp0 = (const float2*)&ks[lane * 34];
        const float2* kp1 = (const float2*)&ks[j2 * 34];

        float acc0[4] = {0.f, 0.f, 0.f, 0.f};
        float acc1[4] = {0.f, 0.f, 0.f, 0.f};
#pragma unroll
        for (int dp = 0; dp < 16; dp++) {
            float2 k0 = kp0[dp];
            float2 k1 = kp1[dp];
            float2 qv;
            qv = q0[dp];
            acc0[0] = fmaf(qv.x, k0.x, acc0[0]); acc0[0] = fmaf(qv.y, k0.y, acc0[0]);
            acc1[0] = fmaf(qv.x, k1.x, acc1[0]); acc1[0] = fmaf(qv.y, k1.y, acc1[0]);
            qv = q1[dp];
            acc0[1] = fmaf(qv.x, k0.x, acc0[1]); acc0[1] = fmaf(qv.y, k0.y, acc0[1]);
            acc1[1] = fmaf(qv.x, k1.x, acc1[1]); acc1[1] = fmaf(qv.y, k1.y, acc1[1]);
            qv = q2c[dp];
            acc0[2] = fmaf(qv.x, k0.x, acc0[2]); acc0[2] = fmaf(qv.y, k0.y, acc0[2]);
            acc1[2] = fmaf(qv.x, k1.x, acc1[2]); acc1[2] = fmaf(qv.y, k1.y, acc1[2]);
            qv = q3[dp];
            acc0[3] = fmaf(qv.x, k0.x, acc0[3]); acc0[3] = fmaf(qv.y, k0.y, acc0[3]);
            acc1[3] = fmaf(qv.x, k1.x, acc1[3]); acc1[3] = fmaf(qv.y, k1.y, acc1[3]);
        }

        // softmax per row
#pragma unroll
        for (int r = 0; r < 4; r++) {
            unsigned long long mb = mbs[rc[r]];
            float x0 = acc0[r] * SCALE_F + bs[rc[r] * LTOK + lane];
            if ((mb >> lane) & 1ull) x0 = -100.0f;
            float x1 = -3.0e38f;
            if (valid1) {
                x1 = acc1[r] * SCALE_F + bs[rc[r] * LTOK + lane + 32];
                if ((mb >> (lane + 32)) & 1ull) x1 = -100.0f;
            }
            float mx = fmaxf(x0, x1);
#pragma unroll
            for (int off = 16; off; off >>= 1)
                mx = fmaxf(mx, __shfl_xor_sync(0xFFFFFFFFu, mx, off));
            float e0 = __expf(x0 - mx);
            float e1 = valid1 ? __expf(x1 - mx) : 0.0f;
            float s = e0 + e1;
#pragma unroll
            for (int off = 16; off; off >>= 1)
                s += __shfl_xor_sync(0xFFFFFFFFu, s, off);
            float inv = 1.0f / s;
            prow[warp][r][lane] = e0 * inv;
            if (valid1) prow[warp][r][lane + 32] = e1 * inv;
        }
        __syncwarp();

        // AV: lane = head-dim, float2 probability broadcasts
        float out[4] = {0.f, 0.f, 0.f, 0.f};
        const float2* p0 = (const float2*)prow[warp][0];
        const float2* p1 = (const float2*)prow[warp][1];
        const float2* p2 = (const float2*)prow[warp][2];
        const float2* p3 = (const float2*)prow[warp][3];
#pragma unroll
        for (int jp = 0; jp < 24; jp++) {
            float v0 = vs[(2 * jp) * 33 + lane];
            float v1 = vs[(2 * jp + 1) * 33 + lane];
            float2 pv;
            pv = p0[jp]; out[0] = fmaf(pv.x, v0, out[0]); out[0] = fmaf(pv.y, v1, out[0]);
            pv = p1[jp]; out[1] = fmaf(pv.x, v0, out[1]); out[1] = fmaf(pv.y, v1, out[1]);
            pv = p2[jp]; out[2] = fmaf(pv.x, v0, out[2]); out[2] = fmaf(pv.y, v1, out[2]);
            pv = p3[jp]; out[3] = fmaf(pv.x, v0, out[3]); out[3] = fmaf(pv.y, v1, out[3]);
        }
        {
            float v48 = vs[48 * 33 + lane];
            out[0] = fmaf(prow[warp][0][48], v48, out[0]);
            out[1] = fmaf(prow[warp][1][48], v48, out[1]);
            out[2] = fmaf(prow[warp][2][48], v48, out[2]);
            out[3] = fmaf(prow[warp][3][48], v48, out[3]);
        }

#pragma unroll
        for (int r = 0; r < 4; r++) {
            int row = row0 + r;
            if (row < LTOK) {
                float o = out[r];
                __nv_bfloat16 hi = __float2bfloat16(o);
                __nv_bfloat16 lo = __float2bfloat16(o - __bfloat162float(hi));
                size_t rb = (size_t)(b * LTOK + row) * KSPL + h * HD + lane;
                a2[rb]            = hi;
                a2[rb + CDIM]     = lo;
                a2[rb + 2 * CDIM] = hi;
            }
        }
        __syncwarp();  // protect prow reuse next sweep
    }
}

// ---------------------------------------------------------------------------
// Launch
// ---------------------------------------------------------------------------
extern "C" void kernel_launch(void* const* d_in, const int* in_sizes, int n_in,
                              void* d_out, int out_size)
{
    const float* x          = (const float*)d_in[0];
    const void*  mask       = d_in[1];
    const float* qkv_w      = (const float*)d_in[2];
    const float* proj_w     = (const float*)d_in[3];
    const float* proj_b     = (const float*)d_in[4];
    const float* rel_bias   = (const float*)d_in[5];
    const int*   rel_coords = (const int*)d_in[6];
    float* out = (float*)d_out;

    float* qkv_s;          cudaGetSymbolAddress((void**)&qkv_s, g_qkv);
    __nv_bfloat16* a1_s;   cudaGetSymbolAddress((void**)&a1_s, g_a1);
    __nv_bfloat16* a2_s;   cudaGetSymbolAddress((void**)&a2_s, g_a2);
    __nv_bfloat16* b1_s;   cudaGetSymbolAddress((void**)&b1_s, g_b1);
    __nv_bfloat16* b2_s;   cudaGetSymbolAddress((void**)&b2_s, g_b2);

    cudaFuncSetAttribute(gemm_mma, cudaFuncAttributeMaxDynamicSharedMemorySize, GSMEM);

    prep_kernel<<<1, 1024>>>(mask, rel_bias, rel_coords);

    split_a_kernel<<<(MTOT * CDIM + 255) / 256, 256>>>(x, a1_s, MTOT * CDIM);
    split_b_kernel<<<(QKVN * CDIM + 255) / 256, 256>>>(qkv_w, b1_s, QKVN * CDIM);
    split_b_kernel<<<(CDIM * CDIM + 255) / 256, 256>>>(proj_w, b2_s, CDIM * CDIM);

    // QKV = x @ qkv_w^T  (M=50176, N=1152, K_eff=1152)
    {
        dim3 grid(QKVN / BN, MTOT / BM);
        gemm_mma<<<grid, 256, GSMEM>>>(a1_s, b1_s, nullptr, qkv_s, QKVN);
    }

    // attention, writing split output directly
    {
        dim3 grid(HEADS, B_WIN);
        attn_kernel<<<grid, 128>>>(qkv_s, a2_s);
    }

    // out = O @ proj_w^T + proj_b  (M=50176, N=384, K_eff=1152)
    {
        dim3 grid(CDIM / BN, MTOT / BM);
        gemm_mma<<<grid, 256, GSMEM>>>(a2_s, b2_s, proj_b, out, CDIM);
    }
}

// round 7
// speedup vs baseline: 1.5010x; 1.5010x over previous
#include <cuda_runtime.h>
#include <cuda_bf16.h>
#include <cstdint>

// Problem constants
#define B_WIN   1024
#define LTOK    49
#define CDIM    384
#define HEADS   12
#define HD      32
#define NWMASK  4
#define MTOT    (B_WIN * LTOK)          // 50176
#define QKVN    (3 * CDIM)              // 1152
#define KSPL    (3 * CDIM)              // 1152: [hi,lo,hi] x [hi,hi,lo] 3-term split
#define SCALE_F 19.595917942265426f     // sqrt(384)

// GEMM tiling — R5-exact (DEPTH=3, cp_wait<1>): known-good 1403us config
#define BM 128
#define BN 128
#define BK 32
#define ROWB 80                          // 32 bf16 = 64B + 16B pad (conflict-free ldmatrix)
#define OPBYTES (128 * ROWB)             // 10240 per operand per stage
#define STG (2 * OPBYTES)                // 20480
#define DEPTH 3
#define NS (KSPL / BK)                   // 36
#define GSMEM (DEPTH * STG)              // 61440

// Scratch (device globals, allocation-free)
__device__ __align__(16) float          g_qkv[(size_t)MTOT * QKVN];   // 231 MB
__device__ __align__(16) __nv_bfloat16  g_a1[(size_t)MTOT * KSPL];    // 116 MB
__device__ __align__(16) __nv_bfloat16  g_a2[(size_t)MTOT * KSPL];    // 116 MB
__device__ __align__(16) __nv_bfloat16  g_b1[(size_t)QKVN * KSPL];    // 2.6 MB
__device__ __align__(16) __nv_bfloat16  g_b2[(size_t)CDIM * KSPL];    // 0.9 MB
__device__ __align__(16) float g_bias[HEADS * LTOK * LTOK];
__device__ unsigned long long g_maskbits[NWMASK * LTOK];

// ---------------------------------------------------------------------------
// Helpers
// ---------------------------------------------------------------------------
__device__ __forceinline__ uint32_t smem_u32(const void* p) {
    uint32_t a;
    asm("{ .reg .u64 t; cvta.to.shared.u64 t, %1; cvt.u32.u64 %0, t; }" : "=r"(a) : "l"(p));
    return a;
}
__device__ __forceinline__ void cp16(uint32_t dst, const void* src) {
    asm volatile("cp.async.cg.shared.global [%0], [%1], 16;" :: "r"(dst), "l"(src) : "memory");
}
__device__ __forceinline__ void cp_commit() { asm volatile("cp.async.commit_group;" ::: "memory"); }
template <int N> __device__ __forceinline__ void cp_wait() {
    asm volatile("cp.async.wait_group %0;" :: "n"(N) : "memory");
}
#define LDSM_X4(r0, r1, r2, r3, addr) \
    asm volatile("ldmatrix.sync.aligned.m8n8.x4.shared.b16 {%0,%1,%2,%3}, [%4];" \
                 : "=r"(r0), "=r"(r1), "=r"(r2), "=r"(r3) : "r"(addr))

__device__ __forceinline__ void mma16816(float* d, const uint32_t* a, const uint32_t* b) {
    asm volatile("mma.sync.aligned.m16n8k16.row.col.f32.bf16.bf16.f32 "
        "{%0,%1,%2,%3}, {%4,%5,%6,%7}, {%8,%9}, {%0,%1,%2,%3};"
        : "+f"(d[0]), "+f"(d[1]), "+f"(d[2]), "+f"(d[3])
        : "r"(a[0]), "r"(a[1]), "r"(a[2]), "r"(a[3]), "r"(b[0]), "r"(b[1]));
}

// ---------------------------------------------------------------------------
// Prep: mask dtype detect + bitmask pack + bias gather (validated)
// ---------------------------------------------------------------------------
__global__ void prep_kernel(const void* __restrict__ mask_raw,
                            const float* __restrict__ rel_bias,
                            const int* __restrict__ rel_coords)
{
    __shared__ int flagBad, flagFloat;
    int tid = threadIdx.x;
    if (tid == 0) { flagBad = 0; flagFloat = 0; }
    __syncthreads();

    const unsigned* mw = (const unsigned*)mask_raw;
    for (int i = tid; i < 2401; i += blockDim.x) {
        unsigned w = mw[i];
        if (w != 0u && w != 1u && w != 0x3F800000u) flagBad = 1;
        if (w == 0x3F800000u) flagFloat = 1;
    }
    __syncthreads();
    int mode = flagBad ? 2 : (flagFloat ? 1 : 0);

    const unsigned char* m8 = (const unsigned char*)mask_raw;
    const float* mf = (const float*)mask_raw;
    const int*   mi = (const int*)mask_raw;

    for (int idx = tid; idx < NWMASK * LTOK; idx += blockDim.x) {
        int w = idx / LTOK, i = idx % LTOK;
        unsigned long long bits = 0ull;
        for (int j = 0; j < LTOK; j++) {
            int g = (w * LTOK + i) * LTOK + j;
            bool v = (mode == 2) ? (m8[g] != 0)
                   : (mode == 1) ? (mf[g] != 0.0f)
                                 : (mi[g] != 0);
            if (v) bits |= (1ull << j);
        }
        g_maskbits[idx] = bits;
    }
    for (int idx = tid; idx < HEADS * LTOK * LTOK; idx += blockDim.x) {
        int h = idx / (LTOK * LTOK);
        int ij = idx % (LTOK * LTOK);
        g_bias[idx] = rel_bias[rel_coords[ij] * HEADS + h];
    }
}

// ---------------------------------------------------------------------------
// bf16 3-term split.  A: [hi, lo, hi]   B: [hi, hi, lo]
// ---------------------------------------------------------------------------
__global__ void split_a_kernel(const float* __restrict__ src,
                               __nv_bfloat16* __restrict__ dst, int total)
{
    int idx = blockIdx.x * blockDim.x + threadIdx.x;
    if (idx >= total) return;
    int r = idx / CDIM, c = idx % CDIM;
    float v = src[idx];
    __nv_bfloat16 hi = __float2bfloat16(v);
    __nv_bfloat16 lo = __float2bfloat16(v - __bfloat162float(hi));
    size_t base = (size_t)r * KSPL;
    dst[base + c]            = hi;
    dst[base + CDIM + c]     = lo;
    dst[base + 2 * CDIM + c] = hi;
}
__global__ void split_b_kernel(const float* __restrict__ src,
                               __nv_bfloat16* __restrict__ dst, int total)
{
    int idx = blockIdx.x * blockDim.x + threadIdx.x;
    if (idx >= total) return;
    int r = idx / CDIM, c = idx % CDIM;
    float v = src[idx];
    __nv_bfloat16 hi = __float2bfloat16(v);
    __nv_bfloat16 lo = __float2bfloat16(v - __bfloat162float(hi));
    size_t base = (size_t)r * KSPL;
    dst[base + c]            = hi;
    dst[base + CDIM + c]     = hi;
    dst[base + 2 * CDIM + c] = lo;
}

// ---------------------------------------------------------------------------
// mma.sync bf16 GEMM (TN) — R5-exact. C[m][n] = sum_k A[m][k]*B[n][k] (+bias)
// 128x128 tile, BK=32, 8 warps (4x2), warp tile 32x64, cp.async 3-stage.
// ---------------------------------------------------------------------------
__global__ __launch_bounds__(256, 2)
void gemm_mma(const __nv_bfloat16* __restrict__ A, const __nv_bfloat16* __restrict__ B,
              const float* __restrict__ bias, float* __restrict__ C, int N)
{
    extern __shared__ __align__(16) char smem[];
    const uint32_t sb = smem_u32(smem);
    const int tid = threadIdx.x;
    const int lane = tid & 31, warp = tid >> 5;
    const int wr = warp >> 1, wc = warp & 1;
    const int m0 = blockIdx.y * BM, n0 = blockIdx.x * BN;

    const __nv_bfloat16* Ab = A + (size_t)m0 * KSPL;
    const __nv_bfloat16* Bb = B + (size_t)n0 * KSPL;

    const int lrow  = tid & 127;
    const int lc16a = tid >> 7;

    auto load_stage = [&](int st) {
        uint32_t buf = sb + (st % DEPTH) * STG;
        int kc = st * BK;
#pragma unroll
        for (int i = 0; i < 2; i++) {
            int c16 = lc16a + i * 2;
            uint32_t d = buf + lrow * ROWB + c16 * 16;
            const __nv_bfloat16* s = Ab + (size_t)lrow * KSPL + kc + c16 * 8;
            cp16(d, s);
            cp16(d + OPBYTES, Bb + (size_t)lrow * KSPL + kc + c16 * 8);
        }
        cp_commit();
    };

    float acc[2][8][4];
#pragma unroll
    for (int mt = 0; mt < 2; mt++)
#pragma unroll
        for (int j = 0; j < 8; j++)
#pragma unroll
            for (int q = 0; q < 4; q++) acc[mt][j][q] = 0.0f;

    load_stage(0);
    load_stage(1);

    const uint32_t a_lane = (uint32_t)((wr * 32 + ((lane >> 3) & 1) * 8 + (lane & 7)) * ROWB
                                       + (lane >> 4) * 16);
    const uint32_t b_lane = (uint32_t)(OPBYTES
                                       + (wc * 64 + ((lane >> 4) & 1) * 8 + (lane & 7)) * ROWB
                                       + ((lane >> 3) & 1) * 16);

    for (int s = 0; s < NS; s++) {
        if (s == NS - 1) cp_wait<0>(); else cp_wait<1>();
        __syncthreads();
        if (s + 2 < NS) load_stage(s + 2);

        uint32_t buf = sb + (s % DEPTH) * STG;
#pragma unroll
        for (int ks = 0; ks < 2; ks++) {
            uint32_t ra[2][4];
#pragma unroll
            for (int mt = 0; mt < 2; mt++)
                LDSM_X4(ra[mt][0], ra[mt][1], ra[mt][2], ra[mt][3],
                        buf + a_lane + mt * 16 * ROWB + ks * 32);
            uint32_t rb[8][2];
#pragma unroll
            for (int nt = 0; nt < 4; nt++) {
                uint32_t r0, r1, r2, r3;
                LDSM_X4(r0, r1, r2, r3, buf + b_lane + nt * 16 * ROWB + ks * 32);
                rb[2 * nt][0] = r0; rb[2 * nt][1] = r1;
                rb[2 * nt + 1][0] = r2; rb[2 * nt + 1][1] = r3;
            }
#pragma unroll
            for (int mt = 0; mt < 2; mt++)
#pragma unroll
                for (int j = 0; j < 8; j++)
                    mma16816(acc[mt][j], ra[mt], rb[j]);
        }
    }

    const int g = lane >> 2, tq = lane & 3;
#pragma unroll
    for (int mt = 0; mt < 2; mt++) {
        int r0 = m0 + wr * 32 + mt * 16 + g;
#pragma unroll
        for (int j = 0; j < 8; j++) {
            int c0 = n0 + wc * 64 + j * 8 + 2 * tq;
            float2 v0 = make_float2(acc[mt][j][0], acc[mt][j][1]);
            float2 v1 = make_float2(acc[mt][j][2], acc[mt][j][3]);
            if (bias) {
                float b0 = bias[c0], b1 = bias[c0 + 1];
                v0.x += b0; v0.y += b1; v1.x += b0; v1.y += b1;
            }
            *(float2*)(C + (size_t)r0 * N + c0)       = v0;
            *(float2*)(C + (size_t)(r0 + 8) * N + c0) = v1;
        }
    }
}

// ---------------------------------------------------------------------------
// Fused window attention v2: register-blocked, 4 query rows per warp per
// sweep. Writes bf16 3-term split output directly ([hi, lo, hi]).
// ---------------------------------------------------------------------------
__global__ __launch_bounds__(128)
void attn_kernel(const float* __restrict__ qkv, __nv_bfloat16* __restrict__ a2)
{
    const int h = blockIdx.x;
    const int b = blockIdx.y;
    const int tid = threadIdx.x;

    __shared__ __align__(16) float qs[LTOK * 34];   // pad 34: float2-aligned rows
    __shared__ __align__(16) float ks[LTOK * 34];
    __shared__ __align__(16) float vs[LTOK * 33];   // pad 33: conflict-free scalar
    __shared__ float bs[LTOK * LTOK];
    __shared__ __align__(16) float prow[4][4][64];  // [warp][r][j]
    __shared__ unsigned long long mbs[LTOK];

    const float* base = qkv + (size_t)(b * LTOK) * QKVN + h * HD;
    for (int t = tid; t < LTOK * HD; t += 128) {
        int l = t >> 5, d = t & 31;
        qs[l * 34 + d] = base[(size_t)l * QKVN + d];
        ks[l * 34 + d] = base[(size_t)l * QKVN + CDIM + d];
        vs[l * 33 + d] = base[(size_t)l * QKVN + 2 * CDIM + d];
    }
    for (int t = tid; t < LTOK * LTOK; t += 128)
        bs[t] = g_bias[h * LTOK * LTOK + t];
    if (tid < LTOK) mbs[tid] = g_maskbits[(b & 3) * LTOK + tid];
    __syncthreads();

    const int warp = tid >> 5;
    const int lane = tid & 31;
    const bool valid1 = (lane + 32) < LTOK;
    const int j2 = valid1 ? lane + 32 : 0;

    for (int sweep = 0; sweep < 4; sweep++) {
        const int row0 = sweep * 16 + warp * 4;
        if (row0 >= LTOK) break;   // uniform per warp

        int rc[4];
#pragma unroll
        for (int r = 0; r < 4; r++) rc[r] = (row0 + r < LTOK) ? row0 + r : LTOK - 1;

        const float2* q0 = (const float2*)&qs[rc[0] * 34];
        const float2* q1 = (const float2*)&qs[rc[1] * 34];
        const float2* q2c = (const float2*)&qs[rc[2] * 34];
        const float2* q3 = (const float2*)&qs[rc[3] * 34];
        const float2* kp0 = (const float2*)&ks[lane * 34];
        const float2* kp1 = (const float2*)&ks[j2 * 34];

        float acc0[4] = {0.f, 0.f, 0.f, 0.f};
        float acc1[4] = {0.f, 0.f, 0.f, 0.f};
#pragma unroll
        for (int dp = 0; dp < 16; dp++) {
            float2 k0 = kp0[dp];
            float2 k1 = kp1[dp];
            float2 qv;
            qv = q0[dp];
            acc0[0] = fmaf(qv.x, k0.x, acc0[0]); acc0[0] = fmaf(qv.y, k0.y, acc0[0]);
            acc1[0] = fmaf(qv.x, k1.x, acc1[0]); acc1[0] = fmaf(qv.y, k1.y, acc1[0]);
            qv = q1[dp];
            acc0[1] = fmaf(qv.x, k0.x, acc0[1]); acc0[1] = fmaf(qv.y, k0.y, acc0[1]);
            acc1[1] = fmaf(qv.x, k1.x, acc1[1]); acc1[1] = fmaf(qv.y, k1.y, acc1[1]);
            qv = q2c[dp];
            acc0[2] = fmaf(qv.x, k0.x, acc0[2]); acc0[2] = fmaf(qv.y, k0.y, acc0[2]);
            acc1[2] = fmaf(qv.x, k1.x, acc1[2]); acc1[2] = fmaf(qv.y, k1.y, acc1[2]);
            qv = q3[dp];
            acc0[3] = fmaf(qv.x, k0.x, acc0[3]); acc0[3] = fmaf(qv.y, k0.y, acc0[3]);
            acc1[3] = fmaf(qv.x, k1.x, acc1[3]); acc1[3] = fmaf(qv.y, k1.y, acc1[3]);
        }

        // softmax per row
#pragma unroll
        for (int r = 0; r < 4; r++) {
            unsigned long long mb = mbs[rc[r]];
            float x0 = acc0[r] * SCALE_F + bs[rc[r] * LTOK + lane];
            if ((mb >> lane) & 1ull) x0 = -100.0f;
            float x1 = -3.0e38f;
            if (valid1) {
                x1 = acc1[r] * SCALE_F + bs[rc[r] * LTOK + lane + 32];
                if ((mb >> (lane + 32)) & 1ull) x1 = -100.0f;
            }
            float mx = fmaxf(x0, x1);
#pragma unroll
            for (int off = 16; off; off >>= 1)
                mx = fmaxf(mx, __shfl_xor_sync(0xFFFFFFFFu, mx, off));
            float e0 = __expf(x0 - mx);
            float e1 = valid1 ? __expf(x1 - mx) : 0.0f;
            float s = e0 + e1;
#pragma unroll
            for (int off = 16; off; off >>= 1)
                s += __shfl_xor_sync(0xFFFFFFFFu, s, off);
            float inv = 1.0f / s;
            prow[warp][r][lane] = e0 * inv;
            if (valid1) prow[warp][r][lane + 32] = e1 * inv;
        }
        __syncwarp();

        // AV: lane = head-dim, float2 probability broadcasts
        float out[4] = {0.f, 0.f, 0.f, 0.f};
        const float2* p0 = (const float2*)prow[warp][0];
        const float2* p1 = (const float2*)prow[warp][1];
        const float2* p2 = (const float2*)prow[warp][2];
        const float2* p3 = (const float2*)prow[warp][3];
#pragma unroll
        for (int jp = 0; jp < 24; jp++) {
            float v0 = vs[(2 * jp) * 33 + lane];
            float v1 = vs[(2 * jp + 1) * 33 + lane];
            float2 pv;
            pv = p0[jp]; out[0] = fmaf(pv.x, v0, out[0]); out[0] = fmaf(pv.y, v1, out[0]);
            pv = p1[jp]; out[1] = fmaf(pv.x, v0, out[1]); out[1] = fmaf(pv.y, v1, out[1]);
            pv = p2[jp]; out[2] = fmaf(pv.x, v0, out[2]); out[2] = fmaf(pv.y, v1, out[2]);
            pv = p3[jp]; out[3] = fmaf(pv.x, v0, out[3]); out[3] = fmaf(pv.y, v1, out[3]);
        }
        {
            float v48 = vs[48 * 33 + lane];
            out[0] = fmaf(prow[warp][0][48], v48, out[0]);
            out[1] = fmaf(prow[warp][1][48], v48, out[1]);
            out[2] = fmaf(prow[warp][2][48], v48, out[2]);
            out[3] = fmaf(prow[warp][3][48], v48, out[3]);
        }

#pragma unroll
        for (int r = 0; r < 4; r++) {
            int row = row0 + r;
            if (row < LTOK) {
                float o = out[r];
                __nv_bfloat16 hi = __float2bfloat16(o);
                __nv_bfloat16 lo = __float2bfloat16(o - __bfloat162float(hi));
                size_t rb = (size_t)(b * LTOK + row) * KSPL + h * HD + lane;
                a2[rb]            = hi;
                a2[rb + CDIM]     = lo;
                a2[rb + 2 * CDIM] = hi;
            }
        }
        __syncwarp();  // protect prow reuse next sweep
    }
}

// ---------------------------------------------------------------------------
// Launch
// ---------------------------------------------------------------------------
extern "C" void kernel_launch(void* const* d_in, const int* in_sizes, int n_in,
                              void* d_out, int out_size)
{
    const float* x          = (const float*)d_in[0];
    const void*  mask       = d_in[1];
    const float* qkv_w      = (const float*)d_in[2];
    const float* proj_w     = (const float*)d_in[3];
    const float* proj_b     = (const float*)d_in[4];
    const float* rel_bias   = (const float*)d_in[5];
    const int*   rel_coords = (const int*)d_in[6];
    float* out = (float*)d_out;

    float* qkv_s;          cudaGetSymbolAddress((void**)&qkv_s, g_qkv);
    __nv_bfloat16* a1_s;   cudaGetSymbolAddress((void**)&a1_s, g_a1);
    __nv_bfloat16* a2_s;   cudaGetSymbolAddress((void**)&a2_s, g_a2);
    __nv_bfloat16* b1_s;   cudaGetSymbolAddress((void**)&b1_s, g_b1);
    __nv_bfloat16* b2_s;   cudaGetSymbolAddress((void**)&b2_s, g_b2);

    cudaFuncSetAttribute(gemm_mma, cudaFuncAttributeMaxDynamicSharedMemorySize, GSMEM);

    prep_kernel<<<1, 1024>>>(mask, rel_bias, rel_coords);

    split_a_kernel<<<(MTOT * CDIM + 255) / 256, 256>>>(x, a1_s, MTOT * CDIM);
    split_b_kernel<<<(QKVN * CDIM + 255) / 256, 256>>>(qkv_w, b1_s, QKVN * CDIM);
    split_b_kernel<<<(CDIM * CDIM + 255) / 256, 256>>>(proj_w, b2_s, CDIM * CDIM);

    // QKV = x @ qkv_w^T  (M=50176, N=1152, K_eff=1152)
    {
        dim3 grid(QKVN / BN, MTOT / BM);
        gemm_mma<<<grid, 256, GSMEM>>>(a1_s, b1_s, nullptr, qkv_s, QKVN);
    }

    // attention, writing split output directly
    {
        dim3 grid(HEADS, B_WIN);
        attn_kernel<<<grid, 128>>>(qkv_s, a2_s);
    }

    // out = O @ proj_w^T + proj_b  (M=50176, N=384, K_eff=1152)
    {
        dim3 grid(CDIM / BN, MTOT / BM);
        gemm_mma<<<grid, 256, GSMEM>>>(a2_s, b2_s, proj_b, out, CDIM);
    }
}

// round 8
// speedup vs baseline: 1.6006x; 1.0663x over previous
#include <cuda_runtime.h>
#include <cuda_bf16.h>
#include <cstdint>

// Problem constants
#define B_WIN   1024
#define LTOK    49
#define CDIM    384
#define HEADS   12
#define HD      32
#define NWMASK  4
#define MTOT    (B_WIN * LTOK)          // 50176
#define QKVN    (3 * CDIM)              // 1152
#define KSPL    (3 * CDIM)              // 1152: [hi,lo,hi] x [hi,hi,lo] 3-term split
#define SCALE_F 19.595917942265426f     // sqrt(384)

// GEMM tiling — R5/R7-exact (DEPTH=3, cp_wait<1>): known-good config. FROZEN.
#define BM 128
#define BN 128
#define BK 32
#define ROWB 80
#define OPBYTES (128 * ROWB)
#define STG (2 * OPBYTES)
#define DEPTH 3
#define NS (KSPL / BK)
#define GSMEM (DEPTH * STG)

// Scratch (device globals, allocation-free)
__device__ __align__(16) float          g_qkv[(size_t)MTOT * QKVN];
__device__ __align__(16) __nv_bfloat16  g_a1[(size_t)MTOT * KSPL];
__device__ __align__(16) __nv_bfloat16  g_a2[(size_t)MTOT * KSPL];
__device__ __align__(16) __nv_bfloat16  g_b1[(size_t)QKVN * KSPL];
__device__ __align__(16) __nv_bfloat16  g_b2[(size_t)CDIM * KSPL];
__device__ __align__(16) float g_bias[HEADS * LTOK * LTOK];
__device__ unsigned long long g_maskbits[NWMASK * LTOK];

// ---------------------------------------------------------------------------
// Helpers
// ---------------------------------------------------------------------------
__device__ __forceinline__ uint32_t smem_u32(const void* p) {
    uint32_t a;
    asm("{ .reg .u64 t; cvta.to.shared.u64 t, %1; cvt.u32.u64 %0, t; }" : "=r"(a) : "l"(p));
    return a;
}
__device__ __forceinline__ void cp16(uint32_t dst, const void* src) {
    asm volatile("cp.async.cg.shared.global [%0], [%1], 16;" :: "r"(dst), "l"(src) : "memory");
}
__device__ __forceinline__ void cp_commit() { asm volatile("cp.async.commit_group;" ::: "memory"); }
template <int N> __device__ __forceinline__ void cp_wait() {
    asm volatile("cp.async.wait_group %0;" :: "n"(N) : "memory");
}
#define LDSM_X4(r0, r1, r2, r3, addr) \
    asm volatile("ldmatrix.sync.aligned.m8n8.x4.shared.b16 {%0,%1,%2,%3}, [%4];" \
                 : "=r"(r0), "=r"(r1), "=r"(r2), "=r"(r3) : "r"(addr))
#define LDSM_X4_T(r0, r1, r2, r3, addr) \
    asm volatile("ldmatrix.sync.aligned.m8n8.x4.trans.shared.b16 {%0,%1,%2,%3}, [%4];" \
                 : "=r"(r0), "=r"(r1), "=r"(r2), "=r"(r3) : "r"(addr))

__device__ __forceinline__ void mma16816(float* d, const uint32_t* a, const uint32_t* b) {
    asm volatile("mma.sync.aligned.m16n8k16.row.col.f32.bf16.bf16.f32 "
        "{%0,%1,%2,%3}, {%4,%5,%6,%7}, {%8,%9}, {%0,%1,%2,%3};"
        : "+f"(d[0]), "+f"(d[1]), "+f"(d[2]), "+f"(d[3])
        : "r"(a[0]), "r"(a[1]), "r"(a[2]), "r"(a[3]), "r"(b[0]), "r"(b[1]));
}
// pack two floats into bf16x2: low half = first arg
__device__ __forceinline__ uint32_t pkbf2(float lo, float hi) {
    uint32_t r;
    asm("cvt.rn.bf16x2.f32 %0, %1, %2;" : "=r"(r) : "f"(hi), "f"(lo));
    return r;
}
__device__ __forceinline__ float bfround(float v) {
    return __bfloat162float(__float2bfloat16(v));
}

// ---------------------------------------------------------------------------
// Prep: mask dtype detect + bitmask pack + bias gather (validated)
// ---------------------------------------------------------------------------
__global__ void prep_kernel(const void* __restrict__ mask_raw,
                            const float* __restrict__ rel_bias,
                            const int* __restrict__ rel_coords)
{
    __shared__ int flagBad, flagFloat;
    int tid = threadIdx.x;
    if (tid == 0) { flagBad = 0; flagFloat = 0; }
    __syncthreads();

    const unsigned* mw = (const unsigned*)mask_raw;
    for (int i = tid; i < 2401; i += blockDim.x) {
        unsigned w = mw[i];
        if (w != 0u && w != 1u && w != 0x3F800000u) flagBad = 1;
        if (w == 0x3F800000u) flagFloat = 1;
    }
    __syncthreads();
    int mode = flagBad ? 2 : (flagFloat ? 1 : 0);

    const unsigned char* m8 = (const unsigned char*)mask_raw;
    const float* mf = (const float*)mask_raw;
    const int*   mi = (const int*)mask_raw;

    for (int idx = tid; idx < NWMASK * LTOK; idx += blockDim.x) {
        int w = idx / LTOK, i = idx % LTOK;
        unsigned long long bits = 0ull;
        for (int j = 0; j < LTOK; j++) {
            int g = (w * LTOK + i) * LTOK + j;
            bool v = (mode == 2) ? (m8[g] != 0)
                   : (mode == 1) ? (mf[g] != 0.0f)
                                 : (mi[g] != 0);
            if (v) bits |= (1ull << j);
        }
        g_maskbits[idx] = bits;
    }
    for (int idx = tid; idx < HEADS * LTOK * LTOK; idx += blockDim.x) {
        int h = idx / (LTOK * LTOK);
        int ij = idx % (LTOK * LTOK);
        g_bias[idx] = rel_bias[rel_coords[ij] * HEADS + h];
    }
}

// ---------------------------------------------------------------------------
// bf16 3-term split.  A: [hi, lo, hi]   B: [hi, hi, lo]
// ---------------------------------------------------------------------------
__global__ void split_a_kernel(const float* __restrict__ src,
                               __nv_bfloat16* __restrict__ dst, int total)
{
    int idx = blockIdx.x * blockDim.x + threadIdx.x;
    if (idx >= total) return;
    int r = idx / CDIM, c = idx % CDIM;
    float v = src[idx];
    __nv_bfloat16 hi = __float2bfloat16(v);
    __nv_bfloat16 lo = __float2bfloat16(v - __bfloat162float(hi));
    size_t base = (size_t)r * KSPL;
    dst[base + c]            = hi;
    dst[base + CDIM + c]     = lo;
    dst[base + 2 * CDIM + c] = hi;
}
__global__ void split_b_kernel(const float* __restrict__ src,
                               __nv_bfloat16* __restrict__ dst, int total)
{
    int idx = blockIdx.x * blockDim.x + threadIdx.x;
    if (idx >= total) return;
    int r = idx / CDIM, c = idx % CDIM;
    float v = src[idx];
    __nv_bfloat16 hi = __float2bfloat16(v);
    __nv_bfloat16 lo = __float2bfloat16(v - __bfloat162float(hi));
    size_t base = (size_t)r * KSPL;
    dst[base + c]            = hi;
    dst[base + CDIM + c]     = hi;
    dst[base + 2 * CDIM + c] = lo;
}

// ---------------------------------------------------------------------------
// mma.sync bf16 GEMM (TN) — FROZEN R7 config.
// ---------------------------------------------------------------------------
__global__ __launch_bounds__(256, 2)
void gemm_mma(const __nv_bfloat16* __restrict__ A, const __nv_bfloat16* __restrict__ B,
              const float* __restrict__ bias, float* __restrict__ C, int N)
{
    extern __shared__ __align__(16) char smem[];
    const uint32_t sb = smem_u32(smem);
    const int tid = threadIdx.x;
    const int lane = tid & 31, warp = tid >> 5;
    const int wr = warp >> 1, wc = warp & 1;
    const int m0 = blockIdx.y * BM, n0 = blockIdx.x * BN;

    const __nv_bfloat16* Ab = A + (size_t)m0 * KSPL;
    const __nv_bfloat16* Bb = B + (size_t)n0 * KSPL;

    const int lrow  = tid & 127;
    const int lc16a = tid >> 7;

    auto load_stage = [&](int st) {
        uint32_t buf = sb + (st % DEPTH) * STG;
        int kc = st * BK;
#pragma unroll
        for (int i = 0; i < 2; i++) {
            int c16 = lc16a + i * 2;
            uint32_t d = buf + lrow * ROWB + c16 * 16;
            const __nv_bfloat16* s = Ab + (size_t)lrow * KSPL + kc + c16 * 8;
            cp16(d, s);
            cp16(d + OPBYTES, Bb + (size_t)lrow * KSPL + kc + c16 * 8);
        }
        cp_commit();
    };

    float acc[2][8][4];
#pragma unroll
    for (int mt = 0; mt < 2; mt++)
#pragma unroll
        for (int j = 0; j < 8; j++)
#pragma unroll
            for (int q = 0; q < 4; q++) acc[mt][j][q] = 0.0f;

    load_stage(0);
    load_stage(1);

    const uint32_t a_lane = (uint32_t)((wr * 32 + ((lane >> 3) & 1) * 8 + (lane & 7)) * ROWB
                                       + (lane >> 4) * 16);
    const uint32_t b_lane = (uint32_t)(OPBYTES
                                       + (wc * 64 + ((lane >> 4) & 1) * 8 + (lane & 7)) * ROWB
                                       + ((lane >> 3) & 1) * 16);

    for (int s = 0; s < NS; s++) {
        if (s == NS - 1) cp_wait<0>(); else cp_wait<1>();
        __syncthreads();
        if (s + 2 < NS) load_stage(s + 2);

        uint32_t buf = sb + (s % DEPTH) * STG;
#pragma unroll
        for (int ks = 0; ks < 2; ks++) {
            uint32_t ra[2][4];
#pragma unroll
            for (int mt = 0; mt < 2; mt++)
                LDSM_X4(ra[mt][0], ra[mt][1], ra[mt][2], ra[mt][3],
                        buf + a_lane + mt * 16 * ROWB + ks * 32);
            uint32_t rb[8][2];
#pragma unroll
            for (int nt = 0; nt < 4; nt++) {
                uint32_t r0, r1, r2, r3;
                LDSM_X4(r0, r1, r2, r3, buf + b_lane + nt * 16 * ROWB + ks * 32);
                rb[2 * nt][0] = r0; rb[2 * nt][1] = r1;
                rb[2 * nt + 1][0] = r2; rb[2 * nt + 1][1] = r3;
            }
#pragma unroll
            for (int mt = 0; mt < 2; mt++)
#pragma unroll
                for (int j = 0; j < 8; j++)
                    mma16816(acc[mt][j], ra[mt], rb[j]);
        }
    }

    const int g = lane >> 2, tq = lane & 3;
#pragma unroll
    for (int mt = 0; mt < 2; mt++) {
        int r0 = m0 + wr * 32 + mt * 16 + g;
#pragma unroll
        for (int j = 0; j < 8; j++) {
            int c0 = n0 + wc * 64 + j * 8 + 2 * tq;
            float2 v0 = make_float2(acc[mt][j][0], acc[mt][j][1]);
            float2 v1 = make_float2(acc[mt][j][2], acc[mt][j][3]);
            if (bias) {
                float b0 = bias[c0], b1 = bias[c0 + 1];
                v0.x += b0; v0.y += b1; v1.x += b0; v1.y += b1;
            }
            *(float2*)(C + (size_t)r0 * N + c0)       = v0;
            *(float2*)(C + (size_t)(r0 + 8) * N + c0) = v1;
        }
    }
}

// ---------------------------------------------------------------------------
// Tensor-core window attention: one (b,h) per 128-thr block.
// QK^T: Q'[64x96]=[hi,lo,hi], K'[64x96]=[hi,hi,lo] bf16, mma m16n8k16.
// Softmax in mma-C register layout (row = 4 lanes, shfl_xor 1,2).
// AV: P stays in registers (C-frag == A-frag), 2-term P x 2-term V (3 products).
// Output written as bf16 3-term split [hi,lo,hi] into proj A operand.
// ---------------------------------------------------------------------------
#define PQ 104   // Q'/K' row pitch in bf16 elems (208 B: 13x16B, conflict-free)
#define PV 40    // V row pitch in bf16 elems (80 B: 5x16B, conflict-free)

__global__ __launch_bounds__(128)
void attn_mma_kernel(const float* __restrict__ qkv, __nv_bfloat16* __restrict__ a2)
{
    const int h = blockIdx.x;
    const int b = blockIdx.y;
    const int tid = threadIdx.x;
    const int lane = tid & 31;
    const int w = tid >> 5;

    __shared__ __align__(16) __nv_bfloat16 qsm[64 * PQ];
    __shared__ __align__(16) __nv_bfloat16 ksm[64 * PQ];
    __shared__ __align__(16) __nv_bfloat16 vhm[64 * PV];
    __shared__ __align__(16) __nv_bfloat16 vlm[64 * PV];
    __shared__ __align__(8) float bsm[LTOK * 52];
    __shared__ unsigned long long mbs[LTOK];

    // ---- load + convert + split ----
    const float* base = qkv + (size_t)(b * LTOK) * QKVN + h * HD;
    for (int t = tid; t < 784; t += 128) {          // 49 rows x 16 float2
        int l = t >> 4, d2 = t & 15;
        const float* rp = base + (size_t)l * QKVN + 2 * d2;
        float2 q = *(const float2*)(rp);
        float2 k = *(const float2*)(rp + CDIM);
        float2 v = *(const float2*)(rp + 2 * CDIM);

        uint32_t qh = pkbf2(q.x, q.y);
        uint32_t ql = pkbf2(q.x - bfround(q.x), q.y - bfround(q.y));
        uint32_t kh = pkbf2(k.x, k.y);
        uint32_t kl = pkbf2(k.x - bfround(k.x), k.y - bfround(k.y));
        uint32_t vh = pkbf2(v.x, v.y);
        uint32_t vl = pkbf2(v.x - bfround(v.x), v.y - bfround(v.y));

        uint32_t* qr = (uint32_t*)&qsm[l * PQ];
        qr[d2] = qh;  qr[16 + d2] = ql;  qr[32 + d2] = qh;   // [hi, lo, hi]
        uint32_t* kr = (uint32_t*)&ksm[l * PQ];
        kr[d2] = kh;  kr[16 + d2] = kh;  kr[32 + d2] = kl;   // [hi, hi, lo]
        ((uint32_t*)&vhm[l * PV])[d2] = vh;
        ((uint32_t*)&vlm[l * PV])[d2] = vl;
    }
    // zero padding rows 49..63
    for (int t = tid; t < 15 * 48; t += 128) {      // 48 u32 = 96 elems data region
        int r = 49 + t / 48, c = t % 48;
        ((uint32_t*)&qsm[r * PQ])[c] = 0;
        ((uint32_t*)&ksm[r * PQ])[c] = 0;
    }
    for (int t = tid; t < 15 * 16; t += 128) {
        int r = 49 + t / 16, c = t % 16;
        ((uint32_t*)&vhm[r * PV])[c] = 0;
        ((uint32_t*)&vlm[r * PV])[c] = 0;
    }
    for (int t = tid; t < LTOK * LTOK; t += 128) {
        int i = t / LTOK, j = t % LTOK;
        bsm[i * 52 + j] = g_bias[h * LTOK * LTOK + t];
    }
    if (tid < LTOK) mbs[tid] = g_maskbits[(b & 3) * LTOK + tid];
    __syncthreads();

    const uint32_t qb = smem_u32(qsm), kb = smem_u32(ksm);
    const uint32_t vhb = smem_u32(vhm), vlb = smem_u32(vlm);
    const int g = lane >> 2, tq = lane & 3;

    // ---- QK^T: warp w computes rows 16w..16w+15 over all 64 key cols ----
    float acc[8][4];
#pragma unroll
    for (int j = 0; j < 8; j++)
#pragma unroll
        for (int q = 0; q < 4; q++) acc[j][q] = 0.0f;

    const uint32_t a_addr = qb + (16 * w + (lane & 15)) * (PQ * 2) + (lane >> 4) * 16;
    const uint32_t b_addr = kb + (((lane >> 4) & 1) * 8 + (lane & 7)) * (PQ * 2)
                               + ((lane >> 3) & 1) * 16;
#pragma unroll
    for (int kc = 0; kc < 6; kc++) {
        uint32_t af[4];
        LDSM_X4(af[0], af[1], af[2], af[3], a_addr + kc * 32);
#pragma unroll
        for (int p = 0; p < 2; p++) {     // 2 pairs of n-tiles per iteration x2
#pragma unroll
            for (int pp = 0; pp < 2; pp++) {
                int pr = p * 2 + pp;      // pair index 0..3 (n-tiles 2pr, 2pr+1)
                uint32_t rb[4];
                LDSM_X4(rb[0], rb[1], rb[2], rb[3],
                        b_addr + pr * 16 * (PQ * 2) + kc * 32);
                mma16816(acc[2 * pr],     af, &rb[0]);
                mma16816(acc[2 * pr + 1], af, &rb[2]);
            }
        }
    }

    // ---- softmax in register layout ----
    const int i0 = 16 * w + g;
    const int i1 = i0 + 8;
    const int ia = (i0 < LTOK) ? i0 : LTOK - 1;
    const int ib = (i1 < LTOK) ? i1 : LTOK - 1;
    const unsigned long long m0 = mbs[ia];
    const unsigned long long m1 = mbs[ib];

    float mx0 = -3.0e38f, mx1 = -3.0e38f;
#pragma unroll
    for (int j = 0; j < 8; j++) {
        int c0 = 8 * j + 2 * tq, c1 = c0 + 1;
        int c0c = (c0 < LTOK) ? c0 : 0, c1c = (c1 < LTOK) ? c1 : 0;
        float v;
        v = acc[j][0] * SCALE_F + bsm[ia * 52 + c0c];
        if ((m0 >> c0) & 1ull) v = -100.0f;
        if (c0 >= LTOK) v = -3.0e38f;
        acc[j][0] = v; mx0 = fmaxf(mx0, v);
        v = acc[j][1] * SCALE_F + bsm[ia * 52 + c1c];
        if ((m0 >> c1) & 1ull) v = -100.0f;
        if (c1 >= LTOK) v = -3.0e38f;
        acc[j][1] = v; mx0 = fmaxf(mx0, v);
        v = acc[j][2] * SCALE_F + bsm[ib * 52 + c0c];
        if ((m1 >> c0) & 1ull) v = -100.0f;
        if (c0 >= LTOK) v = -3.0e38f;
        acc[j][2] = v; mx1 = fmaxf(mx1, v);
        v = acc[j][3] * SCALE_F + bsm[ib * 52 + c1c];
        if ((m1 >> c1) & 1ull) v = -100.0f;
        if (c1 >= LTOK) v = -3.0e38f;
        acc[j][3] = v; mx1 = fmaxf(mx1, v);
    }
    mx0 = fmaxf(mx0, __shfl_xor_sync(0xFFFFFFFFu, mx0, 1));
    mx0 = fmaxf(mx0, __shfl_xor_sync(0xFFFFFFFFu, mx0, 2));
    mx1 = fmaxf(mx1, __shfl_xor_sync(0xFFFFFFFFu, mx1, 1));
    mx1 = fmaxf(mx1, __shfl_xor_sync(0xFFFFFFFFu, mx1, 2));

    float s0 = 0.0f, s1 = 0.0f;
#pragma unroll
    for (int j = 0; j < 8; j++) {
        float e;
        e = __expf(acc[j][0] - mx0); acc[j][0] = e; s0 += e;
        e = __expf(acc[j][1] - mx0); acc[j][1] = e; s0 += e;
        e = __expf(acc[j][2] - mx1); acc[j][2] = e; s1 += e;
        e = __expf(acc[j][3] - mx1); acc[j][3] = e; s1 += e;
    }
    s0 += __shfl_xor_sync(0xFFFFFFFFu, s0, 1);
    s0 += __shfl_xor_sync(0xFFFFFFFFu, s0, 2);
    s1 += __shfl_xor_sync(0xFFFFFFFFu, s1, 1);
    s1 += __shfl_xor_sync(0xFFFFFFFFu, s1, 2);
    const float inv0 = 1.0f / s0, inv1 = 1.0f / s1;

    // ---- P fragments (2-term split), directly in A-fragment layout ----
    uint32_t phi[4][4], plo[4][4];
#pragma unroll
    for (int kc = 0; kc < 4; kc++) {
#pragma unroll
        for (int part = 0; part < 2; part++) {
            int j = 2 * kc + part;
            float p0 = acc[j][0] * inv0, p1 = acc[j][1] * inv0;
            float p2 = acc[j][2] * inv1, p3 = acc[j][3] * inv1;
            phi[kc][2 * part]     = pkbf2(p0, p1);
            phi[kc][2 * part + 1] = pkbf2(p2, p3);
            plo[kc][2 * part]     = pkbf2(p0 - bfround(p0), p1 - bfround(p1));
            plo[kc][2 * part + 1] = pkbf2(p2 - bfround(p2), p3 - bfround(p3));
        }
    }

    // ---- AV: P(2-term) x V(2-term), 3 product terms ----
    float ao[4][4];
#pragma unroll
    for (int n = 0; n < 4; n++)
#pragma unroll
        for (int q = 0; q < 4; q++) ao[n][q] = 0.0f;

    const uint32_t v_lane = (lane & 15) * (PV * 2) + (lane >> 4) * 16;
#pragma unroll
    for (int kc = 0; kc < 4; kc++) {
        uint32_t vh0[4], vh1[4], vl0[4], vl1[4];
        uint32_t vrow = 16 * kc * (PV * 2) + v_lane;
        LDSM_X4_T(vh0[0], vh0[1], vh0[2], vh0[3], vhb + vrow);
        LDSM_X4_T(vh1[0], vh1[1], vh1[2], vh1[3], vhb + vrow + 32);
        LDSM_X4_T(vl0[0], vl0[1], vl0[2], vl0[3], vlb + vrow);
        LDSM_X4_T(vl1[0], vl1[1], vl1[2], vl1[3], vlb + vrow + 32);

        mma16816(ao[0], phi[kc], &vh0[0]);
        mma16816(ao[1], phi[kc], &vh0[2]);
        mma16816(ao[2], phi[kc], &vh1[0]);
        mma16816(ao[3], phi[kc], &vh1[2]);
        mma16816(ao[0], plo[kc], &vh0[0]);
        mma16816(ao[1], plo[kc], &vh0[2]);
        mma16816(ao[2], plo[kc], &vh1[0]);
        mma16816(ao[3], plo[kc], &vh1[2]);
        mma16816(ao[0], phi[kc], &vl0[0]);
        mma16816(ao[1], phi[kc], &vl0[2]);
        mma16816(ao[2], phi[kc], &vl1[0]);
        mma16816(ao[3], phi[kc], &vl1[2]);
    }

    // ---- epilogue: write bf16 3-term split [hi, lo, hi] ----
#pragma unroll
    for (int rr = 0; rr < 2; rr++) {
        int row = (rr == 0) ? i0 : i1;
        if (row < LTOK) {
            uint32_t* dst = (uint32_t*)(a2 + (size_t)(b * LTOK + row) * KSPL
                                        + h * HD + 2 * tq);
#pragma unroll
            for (int n = 0; n < 4; n++) {
                float o0 = ao[n][2 * rr + 0];
                float o1 = ao[n][2 * rr + 1];
                uint32_t hp = pkbf2(o0, o1);
                uint32_t lp = pkbf2(o0 - bfround(o0), o1 - bfround(o1));
                dst[4 * n]       = hp;   // col 8n+2tq, hi block
                dst[4 * n + 192] = lp;   // +CDIM (384 bf16 = 192 u32), lo
                dst[4 * n + 384] = hp;   // +2*CDIM, hi
            }
        }
    }
}

// ---------------------------------------------------------------------------
// Launch
// ---------------------------------------------------------------------------
extern "C" void kernel_launch(void* const* d_in, const int* in_sizes, int n_in,
                              void* d_out, int out_size)
{
    const float* x          = (const float*)d_in[0];
    const void*  mask       = d_in[1];
    const float* qkv_w      = (const float*)d_in[2];
    const float* proj_w     = (const float*)d_in[3];
    const float* proj_b     = (const float*)d_in[4];
    const float* rel_bias   = (const float*)d_in[5];
    const int*   rel_coords = (const int*)d_in[6];
    float* out = (float*)d_out;

    float* qkv_s;          cudaGetSymbolAddress((void**)&qkv_s, g_qkv);
    __nv_bfloat16* a1_s;   cudaGetSymbolAddress((void**)&a1_s, g_a1);
    __nv_bfloat16* a2_s;   cudaGetSymbolAddress((void**)&a2_s, g_a2);
    __nv_bfloat16* b1_s;   cudaGetSymbolAddress((void**)&b1_s, g_b1);
    __nv_bfloat16* b2_s;   cudaGetSymbolAddress((void**)&b2_s, g_b2);

    cudaFuncSetAttribute(gemm_mma, cudaFuncAttributeMaxDynamicSharedMemorySize, GSMEM);

    prep_kernel<<<1, 1024>>>(mask, rel_bias, rel_coords);

    split_a_kernel<<<(MTOT * CDIM + 255) / 256, 256>>>(x, a1_s, MTOT * CDIM);
    split_b_kernel<<<(QKVN * CDIM + 255) / 256, 256>>>(qkv_w, b1_s, QKVN * CDIM);
    split_b_kernel<<<(CDIM * CDIM + 255) / 256, 256>>>(proj_w, b2_s, CDIM * CDIM);

    // QKV = x @ qkv_w^T  (M=50176, N=1152, K_eff=1152)
    {
        dim3 grid(QKVN / BN, MTOT / BM);
        gemm_mma<<<grid, 256, GSMEM>>>(a1_s, b1_s, nullptr, qkv_s, QKVN);
    }

    // tensor-core attention, writing split output directly
    {
        dim3 grid(HEADS, B_WIN);
        attn_mma_kernel<<<grid, 128>>>(qkv_s, a2_s);
    }

    // out = O @ proj_w^T + proj_b  (M=50176, N=384, K_eff=1152)
    {
        dim3 grid(CDIM / BN, MTOT / BM);
        gemm_mma<<<grid, 256, GSMEM>>>(a2_s, b2_s, proj_b, out, CDIM);
    }
}